// round 1
// baseline (speedup 1.0000x reference)
#include <cuda_runtime.h>
#include <math.h>

#define NN 4096
#define ND 256
#define HID 64
#define NH 4
#define NC 16

// ---------------- scratch (static device globals; no runtime allocation) ----
__device__ float  g_H1[NN*ND];      // layer-1 features per head (4 MB)
__device__ float  g_F1[NH*NN];
__device__ float  g_F2[NH*NN];
__device__ float  g_f2max1[NH];
__device__ float4 g_bdf1[NH*NN];    // (f2, B=e^{f2-max}, D=e^{0.01(f2-max)}, 0)
__device__ float  g_H2[NN*ND];      // ELU(attn1 out) (4 MB)
__device__ float  g_G2[NN*NC];      // layer-2 features
__device__ float  g_f1b[NN];
__device__ float  g_f2b[NN];
__device__ float  g_f2max2[1];
__device__ float4 g_bdf2[NN];

// ---------------- packed f32x2 helpers (sm_103a FFMA2) ----------------------
__device__ __forceinline__ unsigned long long pk2(float a, float b){
    unsigned long long r;
    asm("mov.b64 %0, {%1, %2};" : "=l"(r) : "f"(a), "f"(b));
    return r;
}
__device__ __forceinline__ void upk2(unsigned long long v, float& a, float& b){
    asm("mov.b64 {%0, %1}, %2;" : "=f"(a), "=f"(b) : "l"(v));
}
__device__ __forceinline__ void ffma2(unsigned long long& acc,
                                      unsigned long long x, unsigned long long w){
    asm("fma.rn.f32x2 %0, %1, %2, %0;" : "+l"(acc) : "l"(x), "l"(w));
}

// ---------------- K1: H1 = x @ W1_flat^T  (4096x256 @ 256x256^T) ------------
__global__ void gemm1_kernel(const float* __restrict__ X, const float* __restrict__ W){
    __shared__ float sx[64][17];
    __shared__ float sw[64][17];
    int tid = threadIdx.x;            // 256 threads
    int tx = tid & 15, ty = tid >> 4; // 16x16
    int mb = blockIdx.x * 64, nb = blockIdx.y * 64;
    float acc[4][4] = {};
    for (int kb = 0; kb < ND; kb += 16){
        for (int u = tid; u < 64*16; u += 256){
            int m = u >> 4, k = u & 15;
            sx[m][k] = X[(mb + m)*ND + kb + k];
        }
        for (int u = tid; u < 64*16; u += 256){
            int n = u >> 4, k = u & 15;
            sw[n][k] = W[(nb + n)*ND + kb + k];
        }
        __syncthreads();
#pragma unroll
        for (int k = 0; k < 16; k++){
            float a[4], b[4];
#pragma unroll
            for (int r = 0; r < 4; r++){ a[r] = sx[ty*4 + r][k]; b[r] = sw[tx*4 + r][k]; }
#pragma unroll
            for (int i = 0; i < 4; i++)
#pragma unroll
                for (int j = 0; j < 4; j++) acc[i][j] += a[i]*b[j];
        }
        __syncthreads();
    }
#pragma unroll
    for (int i = 0; i < 4; i++)
#pragma unroll
        for (int j = 0; j < 4; j++)
            g_H1[(mb + ty*4 + i)*ND + nb + tx*4 + j] = acc[i][j];
}

// ---------------- K2: f1/f2 per head ----------------------------------------
__global__ void fvec1_kernel(const float* __restrict__ a1, const float* __restrict__ a2){
    __shared__ float s1[NH][HID], s2[NH][HID];
    int tid = threadIdx.x;
    s1[tid >> 6][tid & 63] = a1[tid];
    s2[tid >> 6][tid & 63] = a2[tid];
    __syncthreads();
    int idx = blockIdx.x*256 + tid;   // grid 64
    int h = idx >> 12, i = idx & (NN-1);
    const float* hr = g_H1 + i*ND + h*HID;
    float f1 = 0.f, f2 = 0.f;
#pragma unroll 8
    for (int d = 0; d < HID; d++){
        float v = hr[d];
        f1 += v * s1[h][d];
        f2 += v * s2[h][d];
    }
    g_F1[idx] = f1; g_F2[idx] = f2;
}

// ---------------- K3: per-head max of f2 ------------------------------------
__global__ void max1_kernel(){
    __shared__ float sm[256];
    int t = threadIdx.x; int h = t >> 6, l = t & 63;
    float m = -INFINITY;
    for (int j = l; j < NN; j += 64) m = fmaxf(m, g_F2[h*NN + j]);
    sm[t] = m; __syncthreads();
    if (l == 0){
        float mm = -INFINITY;
        for (int k = 0; k < 64; k++) mm = fmaxf(mm, sm[h*64 + k]);
        g_f2max1[h] = mm;
    }
}

// ---------------- K4: (f2, B, D) table per head ------------------------------
__global__ void bdf1_kernel(){
    int idx = blockIdx.x*256 + threadIdx.x;   // grid 64, idx = h*4096 + j
    int h = idx >> 12;
    float f2 = g_F2[idx];
    float d  = f2 - g_f2max1[h];
    g_bdf1[idx] = make_float4(f2, expf(d), expf(0.01f*d), 0.f);
}

// ---------------- K5: layer-1 attention (all 4 heads fused) + ELU ------------
// block: 256 threads = 32 rows x 8 feature-chunks(8 floats). grid 128.
__global__ void attn1_kernel(const int* __restrict__ adj){
    __shared__ int    s_adj[32][129];
    __shared__ float4 s_bdf[NH][128];
    int tid   = threadIdx.x;
    int rloc  = tid >> 3;
    int fbase = (tid & 7) * 8;
    int row   = blockIdx.x * 32 + rloc;

    float f1r[NH], Ar[NH], Cr[NH];
#pragma unroll
    for (int h = 0; h < NH; h++){
        float f1 = g_F1[h*NN + row];
        float t  = f1 + g_f2max1[h];
        float M  = t > 0.f ? t : 0.01f*t;       // row upper bound on e
        f1r[h] = f1;
        Ar[h]  = expf(t - M);                    // pos-branch row factor
        Cr[h]  = expf(0.01f*t - M);              // neg-branch row factor
    }
    unsigned long long acc[NH][4];
    float Z[NH];
#pragma unroll
    for (int h = 0; h < NH; h++){
        Z[h] = 0.f;
#pragma unroll
        for (int q = 0; q < 4; q++) acc[h][q] = 0ull;
    }

    const int* arow = adj + blockIdx.x * 32 * NN;
    for (int j0 = 0; j0 < NN; j0 += 128){
        if (j0) __syncthreads();
        for (int u = tid; u < 32*128; u += 256){
            int rr = u >> 7, cc = u & 127;
            s_adj[rr][cc] = arow[rr*NN + j0 + cc];
        }
        for (int u = tid; u < NH*128; u += 256){
            int h = u >> 7, cc = u & 127;
            s_bdf[h][cc] = g_bdf1[h*NN + j0 + cc];
        }
        __syncthreads();
#pragma unroll 2
        for (int jj = 0; jj < 128; jj++){
            int a = s_adj[rloc][jj];
            const float* hv = g_H1 + (j0 + jj)*ND + fbase;
#pragma unroll
            for (int h = 0; h < NH; h++){
                float4 bdf = s_bdf[h][jj];
                float s = f1r[h] + bdf.x;
                float w = (s > 0.f) ? (Ar[h]*bdf.y) : (Cr[h]*bdf.z);
                if ((a == 0) | (s == 0.f)) w = 0.f;  // adj mask + e==0 -> -inf
                Z[h] += w;
                const ulonglong2* p = reinterpret_cast<const ulonglong2*>(hv + h*HID);
                ulonglong2 q0 = p[0];
                ulonglong2 q1 = p[1];
                unsigned long long wp = pk2(w, w);
                ffma2(acc[h][0], q0.x, wp);
                ffma2(acc[h][1], q0.y, wp);
                ffma2(acc[h][2], q1.x, wp);
                ffma2(acc[h][3], q1.y, wp);
            }
        }
    }
    // epilogue: normalize + ELU, write H2
#pragma unroll
    for (int h = 0; h < NH; h++){
        float rz = 1.f / Z[h];
        float* dst = g_H2 + row*ND + h*HID + fbase;
#pragma unroll
        for (int q = 0; q < 4; q++){
            float x0, x1; upk2(acc[h][q], x0, x1);
            x0 *= rz; x1 *= rz;
            dst[2*q]   = x0 > 0.f ? x0 : expm1f(x0);
            dst[2*q+1] = x1 > 0.f ? x1 : expm1f(x1);
        }
    }
}

// ---------------- K6: G2 = H2 @ W2^T, plus layer-2 f-vectors -----------------
__global__ void gemm2_kernel(const float* __restrict__ W2,
                             const float* __restrict__ a1, const float* __restrict__ a2){
    __shared__ float sW[16][257];
    __shared__ float sa1[16], sa2[16];
    int tid = threadIdx.x;
    for (int u = tid; u < 16*256; u += 256) sW[u >> 8][u & 255] = W2[u];
    if (tid < 16){ sa1[tid] = a1[tid]; sa2[tid] = a2[tid]; }
    __syncthreads();
    int idx = blockIdx.x*256 + tid;   // grid 256
    int i = idx >> 4, c = idx & 15;
    const float4* hr = reinterpret_cast<const float4*>(g_H2 + i*ND);
    float acc = 0.f;
#pragma unroll 4
    for (int k4 = 0; k4 < 64; k4++){
        float4 v = hr[k4];
        acc += v.x*sW[c][k4*4] + v.y*sW[c][k4*4+1] + v.z*sW[c][k4*4+2] + v.w*sW[c][k4*4+3];
    }
    g_G2[idx] = acc;
    float u1 = acc*sa1[c], u2 = acc*sa2[c];
#pragma unroll
    for (int off = 8; off > 0; off >>= 1){
        u1 += __shfl_down_sync(0xffffffffu, u1, off, 16);
        u2 += __shfl_down_sync(0xffffffffu, u2, off, 16);
    }
    if (c == 0){ g_f1b[i] = u1; g_f2b[i] = u2; }
}

// ---------------- K7/K8: layer-2 max + table ---------------------------------
__global__ void max2_kernel(){
    __shared__ float sm[256];
    int t = threadIdx.x; float m = -INFINITY;
    for (int j = t; j < NN; j += 256) m = fmaxf(m, g_f2b[j]);
    sm[t] = m; __syncthreads();
    for (int off = 128; off > 0; off >>= 1){
        if (t < off) sm[t] = fmaxf(sm[t], sm[t + off]);
        __syncthreads();
    }
    if (t == 0) g_f2max2[0] = sm[0];
}
__global__ void bdf2_kernel(){
    int j = blockIdx.x*256 + threadIdx.x;   // grid 16
    float f2 = g_f2b[j];
    float d  = f2 - g_f2max2[0];
    g_bdf2[j] = make_float4(f2, expf(d), expf(0.01f*d), 0.f);
}

// ---------------- K9: layer-2 attention -> logits ----------------------------
// block: 256 threads = 32 rows x 8 j-lanes; grid 128. j split -> smem reduce.
__global__ void attn2_kernel(const int* __restrict__ adj, float* __restrict__ out){
    __shared__ int    s_adj[32][129];
    __shared__ float4 s_bdf[128];
    __shared__ float  sred[32][8][17];
    int tid  = threadIdx.x;
    int rloc = tid >> 3;
    int jl   = tid & 7;
    int row  = blockIdx.x * 32 + rloc;

    float f1 = g_f1b[row];
    float t  = f1 + g_f2max2[0];
    float M  = t > 0.f ? t : 0.01f*t;
    float A  = expf(t - M), C = expf(0.01f*t - M);
    unsigned long long acc[8];
#pragma unroll
    for (int q = 0; q < 8; q++) acc[q] = 0ull;
    float Z = 0.f;

    const int* arow = adj + blockIdx.x * 32 * NN;
    for (int j0 = 0; j0 < NN; j0 += 128){
        if (j0) __syncthreads();
        for (int u = tid; u < 32*128; u += 256){
            int rr = u >> 7, cc = u & 127;
            s_adj[rr][cc] = arow[rr*NN + j0 + cc];
        }
        if (tid < 128) s_bdf[tid] = g_bdf2[j0 + tid];
        __syncthreads();
        for (int jj = jl; jj < 128; jj += 8){
            int a = s_adj[rloc][jj];
            float4 bdf = s_bdf[jj];
            float s = f1 + bdf.x;
            float w = (s > 0.f) ? (A*bdf.y) : (C*bdf.z);
            if ((a == 0) | (s == 0.f)) w = 0.f;
            Z += w;
            const ulonglong2* p = reinterpret_cast<const ulonglong2*>(g_G2 + (j0 + jj)*NC);
            ulonglong2 q0 = p[0], q1 = p[1], q2 = p[2], q3 = p[3];
            unsigned long long wp = pk2(w, w);
            ffma2(acc[0], q0.x, wp); ffma2(acc[1], q0.y, wp);
            ffma2(acc[2], q1.x, wp); ffma2(acc[3], q1.y, wp);
            ffma2(acc[4], q2.x, wp); ffma2(acc[5], q2.y, wp);
            ffma2(acc[6], q3.x, wp); ffma2(acc[7], q3.y, wp);
        }
    }
#pragma unroll
    for (int q = 0; q < 8; q++){
        float x0, x1; upk2(acc[q], x0, x1);
        sred[rloc][jl][2*q]   = x0;
        sred[rloc][jl][2*q+1] = x1;
    }
    sred[rloc][jl][16] = Z;
    __syncthreads();
    for (int u = tid; u < 32*16; u += 256){
        int r = u >> 4, f = u & 15;
        float sum = 0.f, zz = 0.f;
#pragma unroll
        for (int l = 0; l < 8; l++){ sum += sred[r][l][f]; zz += sred[r][l][16]; }
        out[(blockIdx.x*32 + r)*NC + f] = sum / zz;
    }
}

// ---------------- launch ------------------------------------------------------
extern "C" void kernel_launch(void* const* d_in, const int* in_sizes, int n_in,
                              void* d_out, int out_size){
    const float* x    = (const float*)d_in[0];
    const int*   adj  = (const int*)  d_in[1];
    const float* W1   = (const float*)d_in[2];
    const float* a1_1 = (const float*)d_in[3];
    const float* a2_1 = (const float*)d_in[4];
    const float* W2   = (const float*)d_in[5];
    const float* a1_2 = (const float*)d_in[6];
    const float* a2_2 = (const float*)d_in[7];
    float* out = (float*)d_out;

    gemm1_kernel<<<dim3(64, 4), 256>>>(x, W1);
    fvec1_kernel<<<64, 256>>>(a1_1, a2_1);
    max1_kernel<<<1, 256>>>();
    bdf1_kernel<<<64, 256>>>();
    attn1_kernel<<<128, 256>>>(adj);
    gemm2_kernel<<<256, 256>>>(W2, a1_2, a2_2);
    max2_kernel<<<1, 256>>>();
    bdf2_kernel<<<16, 256>>>();
    attn2_kernel<<<128, 256>>>(adj, out);
}

// round 3
// speedup vs baseline: 5.0566x; 5.0566x over previous
#include <cuda_runtime.h>
#include <math.h>

#define NN 4096
#define ND 256
#define HID 64
#define NH 4
#define NC 16
#define S  4            // j-range splits for attn1
#define JS (NN/S)       // 1024 j per split
#define NT (JS/32)      // 32 tiles per block

// ---------------- scratch (static device globals) ---------------------------
__device__ float  g_H1[NN*ND];       // layer-1 features (4 MB)
__device__ float  g_F1[NH*NN];
__device__ float  g_F2[NH*NN];
__device__ float  g_f2max1[NH];
__device__ float4 g_bdf1[NH*NN];     // (f2, B=e^{f2-max}, D=e^{0.01(f2-max)}, 0)
__device__ float  g_P1[S*NN*ND];     // attn1 partial sums (16 MB)
__device__ float  g_Zp[S*NH*NN];     // attn1 partial denominators
__device__ float  g_H2[NN*ND];       // ELU(attn1) (4 MB)
__device__ float  g_G2[NN*NC];
__device__ float  g_f1b[NN];
__device__ float  g_f2b[NN];
__device__ float  g_f2max2[1];
__device__ float4 g_bdf2[NN];

// ---------------- packed f32x2 helpers ---------------------------------------
__device__ __forceinline__ unsigned long long pk2(float a, float b){
    unsigned long long r;
    asm("mov.b64 %0, {%1, %2};" : "=l"(r) : "f"(a), "f"(b));
    return r;
}
__device__ __forceinline__ void upk2(unsigned long long v, float& a, float& b){
    asm("mov.b64 {%0, %1}, %2;" : "=f"(a), "=f"(b) : "l"(v));
}
__device__ __forceinline__ void ffma2(unsigned long long& acc,
                                      unsigned long long x, unsigned long long w){
    asm("fma.rn.f32x2 %0, %1, %2, %0;" : "+l"(acc) : "l"(x), "l"(w));
}

// ---------------- K1: H1 = x @ W1_flat^T -------------------------------------
__global__ void gemm1_kernel(const float* __restrict__ X, const float* __restrict__ W){
    __shared__ float sx[64][17];
    __shared__ float sw[64][17];
    int tid = threadIdx.x;
    int tx = tid & 15, ty = tid >> 4;
    int mb = blockIdx.x * 64, nb = blockIdx.y * 64;
    float acc[4][4] = {};
    for (int kb = 0; kb < ND; kb += 16){
        for (int u = tid; u < 64*16; u += 256){
            int m = u >> 4, k = u & 15;
            sx[m][k] = X[(mb + m)*ND + kb + k];
        }
        for (int u = tid; u < 64*16; u += 256){
            int n = u >> 4, k = u & 15;
            sw[n][k] = W[(nb + n)*ND + kb + k];
        }
        __syncthreads();
#pragma unroll
        for (int k = 0; k < 16; k++){
            float a[4], b[4];
#pragma unroll
            for (int r = 0; r < 4; r++){ a[r] = sx[ty*4 + r][k]; b[r] = sw[tx*4 + r][k]; }
#pragma unroll
            for (int i = 0; i < 4; i++)
#pragma unroll
                for (int j = 0; j < 4; j++) acc[i][j] += a[i]*b[j];
        }
        __syncthreads();
    }
#pragma unroll
    for (int i = 0; i < 4; i++)
#pragma unroll
        for (int j = 0; j < 4; j++)
            g_H1[(mb + ty*4 + i)*ND + nb + tx*4 + j] = acc[i][j];
}

// ---------------- K2: f1/f2 per head -----------------------------------------
__global__ void fvec1_kernel(const float* __restrict__ a1, const float* __restrict__ a2){
    __shared__ float s1[NH][HID], s2[NH][HID];
    int tid = threadIdx.x;
    s1[tid >> 6][tid & 63] = a1[tid];
    s2[tid >> 6][tid & 63] = a2[tid];
    __syncthreads();
    int idx = blockIdx.x*256 + tid;
    int h = idx >> 12, i = idx & (NN-1);
    const float* hr = g_H1 + i*ND + h*HID;
    float f1 = 0.f, f2 = 0.f;
#pragma unroll 8
    for (int d = 0; d < HID; d++){
        float v = hr[d];
        f1 += v * s1[h][d];
        f2 += v * s2[h][d];
    }
    g_F1[idx] = f1; g_F2[idx] = f2;
}

// ---------------- K3: per-head max of f2 -------------------------------------
__global__ void max1_kernel(){
    __shared__ float sm[256];
    int t = threadIdx.x; int h = t >> 6, l = t & 63;
    float m = -INFINITY;
    for (int j = l; j < NN; j += 64) m = fmaxf(m, g_F2[h*NN + j]);
    sm[t] = m; __syncthreads();
    if (l == 0){
        float mm = -INFINITY;
        for (int k = 0; k < 64; k++) mm = fmaxf(mm, sm[h*64 + k]);
        g_f2max1[h] = mm;
    }
}

// ---------------- K4: (f2, B, D) table per head -------------------------------
__global__ void bdf1_kernel(){
    int idx = blockIdx.x*256 + threadIdx.x;
    int h = idx >> 12;
    float f2 = g_F2[idx];
    float d  = f2 - g_f2max1[h];
    g_bdf1[idx] = make_float4(f2, expf(d), expf(0.01f*d), 0.f);
}

// ---------------- K5: layer-1 attention, two-phase tiled ----------------------
// grid (128, S), 256 threads. Rows/block = 32, j-tile = 32, j-range = JS per y.
// dyn smem: sw[4][32][32] | sv[32][256] | sadj[32][33] | sb[4][32]f4 | zsh[4][32][2]
#define SM_SW   0
#define SM_SV   16384
#define SM_ADJ  49152
#define SM_B    53376
#define SM_Z    55424
#define SM_TOT  56448

__global__ void attn1_kernel(const int* __restrict__ adj){
    extern __shared__ char smem[];
    float*  sw   = (float*) (smem + SM_SW);
    float*  sv   = (float*) (smem + SM_SV);
    int*    sadj = (int*)   (smem + SM_ADJ);
    float4* sb   = (float4*)(smem + SM_B);
    float*  zsh  = (float*) (smem + SM_Z);

    int tid  = threadIdx.x;
    int row0 = blockIdx.x * 32;
    int sidx = blockIdx.y;

    // phase-A identity: (head, row, j-half)
    int ah   = tid >> 6;
    int arow = (tid >> 1) & 31;
    int ajh  = tid & 1;
    float f1 = g_F1[ah*NN + row0 + arow];
    float tt = f1 + g_f2max1[ah];
    float M  = tt > 0.f ? tt : 0.01f*tt;
    float Apos = expf(tt - M), Cneg = expf(0.01f*tt - M);
    float Z = 0.f;

    // phase-B identity: 64 fgroups(4 feats) x 4 rgroups(8 rows)
    int fg = tid & 63, rg = tid >> 6;
    int bh = fg >> 4;
    int fb = (fg & 15) * 4;
    unsigned long long acc2[4][4] = {};  // [row-pair][feat]

    const int* arow_ptr = adj + row0*NN;

    for (int t = 0; t < NT; t++){
        int j0 = sidx*JS + t*32;
        __syncthreads();   // protect sv/sadj/sb from phase-B readers of prev tile
        // stage adjacency, transposed [j][row] with pad 33
        {
            int u  = tid * 4;
            int rr = u >> 5, cc = u & 31;
            int4 av = *reinterpret_cast<const int4*>(arow_ptr + rr*NN + j0 + cc);
            sadj[(cc+0)*33 + rr] = av.x;
            sadj[(cc+1)*33 + rr] = av.y;
            sadj[(cc+2)*33 + rr] = av.z;
            sadj[(cc+3)*33 + rr] = av.w;
        }
        // stage v tile: 32 consecutive g_H1 rows (32 KB)
        {
            const float4* gsrc = reinterpret_cast<const float4*>(g_H1 + j0*ND);
            float4* vdst = reinterpret_cast<float4*>(sv);
#pragma unroll
            for (int u = 0; u < 8; u++) vdst[tid + u*256] = gsrc[tid + u*256];
        }
        // stage bdf tile
        if (tid < 128) sb[tid] = g_bdf1[(tid>>5)*NN + j0 + (tid & 31)];
        __syncthreads();   // staged tiles visible before phase A reads them
        // phase A: weights -> smem
#pragma unroll
        for (int q = 0; q < 16; q++){
            int j = ajh*16 + q;
            float4 b = sb[ah*32 + j];
            int a = sadj[j*33 + arow];
            float sc = f1 + b.x;
            float w = sc > 0.f ? Apos*b.y : Cneg*b.z;
            if ((a == 0) | (sc == 0.f)) w = 0.f;
            Z += w;
            sw[(ah*32 + j)*32 + arow] = w;
        }
        __syncthreads();   // weights visible before phase B
        // phase B: accumulate 8 rows x 4 feats
#pragma unroll 4
        for (int j = 0; j < 32; j++){
            const unsigned long long* wq =
                reinterpret_cast<const unsigned long long*>(&sw[(bh*32 + j)*32 + rg*8]);
            unsigned long long w01 = wq[0], w23 = wq[1], w45 = wq[2], w67 = wq[3];
            float4 vv = *reinterpret_cast<const float4*>(&sv[j*256 + bh*64 + fb]);
            unsigned long long v0 = pk2(vv.x, vv.x);
            unsigned long long v1 = pk2(vv.y, vv.y);
            unsigned long long v2 = pk2(vv.z, vv.z);
            unsigned long long v3 = pk2(vv.w, vv.w);
            ffma2(acc2[0][0], w01, v0); ffma2(acc2[0][1], w01, v1);
            ffma2(acc2[0][2], w01, v2); ffma2(acc2[0][3], w01, v3);
            ffma2(acc2[1][0], w23, v0); ffma2(acc2[1][1], w23, v1);
            ffma2(acc2[1][2], w23, v2); ffma2(acc2[1][3], w23, v3);
            ffma2(acc2[2][0], w45, v0); ffma2(acc2[2][1], w45, v1);
            ffma2(acc2[2][2], w45, v2); ffma2(acc2[2][3], w45, v3);
            ffma2(acc2[3][0], w67, v0); ffma2(acc2[3][1], w67, v1);
            ffma2(acc2[3][2], w67, v2); ffma2(acc2[3][3], w67, v3);
        }
    }
    // Z partials
    zsh[(ah*32 + arow)*2 + ajh] = Z;
    __syncthreads();
    if (ajh == 0){
        g_Zp[sidx*NH*NN + ah*NN + row0 + arow] =
            zsh[(ah*32 + arow)*2] + zsh[(ah*32 + arow)*2 + 1];
    }
    // store feature partials
    int pbase = (sidx*NN + row0 + rg*8)*ND + bh*64 + fb;
#pragma unroll
    for (int q = 0; q < 4; q++){
        float l0,h0,l1,h1,l2,h2,l3,h3;
        upk2(acc2[q][0], l0, h0); upk2(acc2[q][1], l1, h1);
        upk2(acc2[q][2], l2, h2); upk2(acc2[q][3], l3, h3);
        *reinterpret_cast<float4*>(&g_P1[pbase + (2*q)*ND])   = make_float4(l0,l1,l2,l3);
        *reinterpret_cast<float4*>(&g_P1[pbase + (2*q+1)*ND]) = make_float4(h0,h1,h2,h3);
    }
}

// ---------------- K5b: combine partials, normalize, ELU -----------------------
__global__ void combine1_kernel(){
    int idx = blockIdx.x*256 + threadIdx.x;   // grid 1024 -> NN*ND/4 float4s
    int o = idx * 4;
    int i = o >> 8, f = o & 255, h = f >> 6;
    float z = 0.f;
#pragma unroll
    for (int s = 0; s < S; s++) z += g_Zp[s*NH*NN + h*NN + i];
    float4 acc = make_float4(0.f,0.f,0.f,0.f);
#pragma unroll
    for (int s = 0; s < S; s++){
        float4 p = *reinterpret_cast<const float4*>(&g_P1[s*NN*ND + o]);
        acc.x += p.x; acc.y += p.y; acc.z += p.z; acc.w += p.w;
    }
    float rz = 1.f / z;
    acc.x *= rz; acc.y *= rz; acc.z *= rz; acc.w *= rz;
    acc.x = acc.x > 0.f ? acc.x : expm1f(acc.x);
    acc.y = acc.y > 0.f ? acc.y : expm1f(acc.y);
    acc.z = acc.z > 0.f ? acc.z : expm1f(acc.z);
    acc.w = acc.w > 0.f ? acc.w : expm1f(acc.w);
    *reinterpret_cast<float4*>(&g_H2[o]) = acc;
}

// ---------------- K6: G2 = H2 @ W2^T + layer-2 f-vectors ----------------------
__global__ void gemm2_kernel(const float* __restrict__ W2,
                             const float* __restrict__ a1, const float* __restrict__ a2){
    __shared__ float sW[16][257];
    __shared__ float sa1[16], sa2[16];
    int tid = threadIdx.x;
    for (int u = tid; u < 16*256; u += 256) sW[u >> 8][u & 255] = W2[u];
    if (tid < 16){ sa1[tid] = a1[tid]; sa2[tid] = a2[tid]; }
    __syncthreads();
    int idx = blockIdx.x*256 + tid;
    int i = idx >> 4, c = idx & 15;
    const float4* hr = reinterpret_cast<const float4*>(g_H2 + i*ND);
    float acc = 0.f;
#pragma unroll 4
    for (int k4 = 0; k4 < 64; k4++){
        float4 v = hr[k4];
        acc += v.x*sW[c][k4*4] + v.y*sW[c][k4*4+1] + v.z*sW[c][k4*4+2] + v.w*sW[c][k4*4+3];
    }
    g_G2[idx] = acc;
    float u1 = acc*sa1[c], u2 = acc*sa2[c];
#pragma unroll
    for (int off = 8; off > 0; off >>= 1){
        u1 += __shfl_down_sync(0xffffffffu, u1, off, 16);
        u2 += __shfl_down_sync(0xffffffffu, u2, off, 16);
    }
    if (c == 0){ g_f1b[i] = u1; g_f2b[i] = u2; }
}

// ---------------- K7/K8: layer-2 max + table ----------------------------------
__global__ void max2_kernel(){
    __shared__ float sm[256];
    int t = threadIdx.x; float m = -INFINITY;
    for (int j = t; j < NN; j += 256) m = fmaxf(m, g_f2b[j]);
    sm[t] = m; __syncthreads();
    for (int off = 128; off > 0; off >>= 1){
        if (t < off) sm[t] = fmaxf(sm[t], sm[t + off]);
        __syncthreads();
    }
    if (t == 0) g_f2max2[0] = sm[0];
}
__global__ void bdf2_kernel(){
    int j = blockIdx.x*256 + threadIdx.x;
    float f2 = g_f2b[j];
    float d  = f2 - g_f2max2[0];
    g_bdf2[j] = make_float4(f2, expf(d), expf(0.01f*d), 0.f);
}

// ---------------- K9: layer-2 attention -> logits -----------------------------
__global__ void attn2_kernel(const int* __restrict__ adj, float* __restrict__ out){
    __shared__ int    s_adj[32][129];
    __shared__ float4 s_bdf[128];
    __shared__ float  sred[32][8][17];
    int tid  = threadIdx.x;
    int rloc = tid >> 3;
    int jl   = tid & 7;
    int row  = blockIdx.x * 32 + rloc;

    float f1 = g_f1b[row];
    float t  = f1 + g_f2max2[0];
    float M  = t > 0.f ? t : 0.01f*t;
    float A  = expf(t - M), C = expf(0.01f*t - M);
    unsigned long long acc[8];
#pragma unroll
    for (int q = 0; q < 8; q++) acc[q] = 0ull;
    float Z = 0.f;

    const int* arow = adj + blockIdx.x * 32 * NN;
    for (int j0 = 0; j0 < NN; j0 += 128){
        if (j0) __syncthreads();
        for (int u = tid; u < 32*128; u += 256){
            int rr = u >> 7, cc = u & 127;
            s_adj[rr][cc] = arow[rr*NN + j0 + cc];
        }
        if (tid < 128) s_bdf[tid] = g_bdf2[j0 + tid];
        __syncthreads();
        for (int jj = jl; jj < 128; jj += 8){
            int a = s_adj[rloc][jj];
            float4 bdf = s_bdf[jj];
            float s = f1 + bdf.x;
            float w = (s > 0.f) ? (A*bdf.y) : (C*bdf.z);
            if ((a == 0) | (s == 0.f)) w = 0.f;
            Z += w;
            const ulonglong2* p = reinterpret_cast<const ulonglong2*>(g_G2 + (j0 + jj)*NC);
            ulonglong2 q0 = p[0], q1 = p[1], q2 = p[2], q3 = p[3];
            unsigned long long wp = pk2(w, w);
            ffma2(acc[0], q0.x, wp); ffma2(acc[1], q0.y, wp);
            ffma2(acc[2], q1.x, wp); ffma2(acc[3], q1.y, wp);
            ffma2(acc[4], q2.x, wp); ffma2(acc[5], q2.y, wp);
            ffma2(acc[6], q3.x, wp); ffma2(acc[7], q3.y, wp);
        }
    }
#pragma unroll
    for (int q = 0; q < 8; q++){
        float x0, x1; upk2(acc[q], x0, x1);
        sred[rloc][jl][2*q]   = x0;
        sred[rloc][jl][2*q+1] = x1;
    }
    sred[rloc][jl][16] = Z;
    __syncthreads();
    for (int u = tid; u < 32*16; u += 256){
        int r = u >> 4, f = u & 15;
        float sum = 0.f, zz = 0.f;
#pragma unroll
        for (int l = 0; l < 8; l++){ sum += sred[r][l][f]; zz += sred[r][l][16]; }
        out[(blockIdx.x*32 + r)*NC + f] = sum / zz;
    }
}

// ---------------- launch ------------------------------------------------------
extern "C" void kernel_launch(void* const* d_in, const int* in_sizes, int n_in,
                              void* d_out, int out_size){
    const float* x    = (const float*)d_in[0];
    const int*   adj  = (const int*)  d_in[1];
    const float* W1   = (const float*)d_in[2];
    const float* a1_1 = (const float*)d_in[3];
    const float* a2_1 = (const float*)d_in[4];
    const float* W2   = (const float*)d_in[5];
    const float* a1_2 = (const float*)d_in[6];
    const float* a2_2 = (const float*)d_in[7];
    float* out = (float*)d_out;

    static int smem_set = 0;
    if (!smem_set){
        cudaFuncSetAttribute(attn1_kernel,
                             cudaFuncAttributeMaxDynamicSharedMemorySize, SM_TOT);
        smem_set = 1;
    }

    gemm1_kernel<<<dim3(64, 4), 256>>>(x, W1);
    fvec1_kernel<<<64, 256>>>(a1_1, a2_1);
    max1_kernel<<<1, 256>>>();
    bdf1_kernel<<<64, 256>>>();
    attn1_kernel<<<dim3(128, S), 256, SM_TOT>>>(adj);
    combine1_kernel<<<1024, 256>>>();
    gemm2_kernel<<<256, 256>>>(W2, a1_2, a2_2);
    max2_kernel<<<1, 256>>>();
    bdf2_kernel<<<16, 256>>>();
    attn2_kernel<<<128, 256>>>(adj, out);
}